// round 2
// baseline (speedup 1.0000x reference)
#include <cuda_runtime.h>
#include <math.h>

#define BB   64
#define TT_  1024
#define DDEC 1024
#define DENC 512
#define AA   512
#define NFF  32
#define KK   31
#define ETOT 544   /* 512 enc + 32 loc features, unified GEMM K dim */

// ---------------- device scratch (no allocations allowed) ----------------
__device__ float g_wT[ETOT * AA];              // [row][a]  row<512: w_enc^T, row>=512: w_loc^T
__device__ float g_locfeat[BB * TT_ * NFF];    // [b][t][f]  conv output
__device__ float g_mel[BB * AA];               // mel_proj (incl. bias)
__device__ float g_energy[BB * TT_];           // pre-softmax energies (masked)
__device__ float g_ctxp[8 * BB * DENC];        // context partials over 8 t-chunks

// ---------------- packed fp32x2 helpers (Blackwell FFMA2) ----------------
__device__ __forceinline__ unsigned long long fma2(unsigned long long a,
                                                   unsigned long long b,
                                                   unsigned long long c) {
    unsigned long long d;
    asm("fma.rn.f32x2 %0, %1, %2, %3;" : "=l"(d) : "l"(a), "l"(b), "l"(c));
    return d;
}
__device__ __forceinline__ unsigned long long pack2(float x, float y) {
    unsigned long long d;
    asm("mov.b64 %0, {%1, %2};" : "=l"(d) : "f"(x), "f"(y));
    return d;
}
__device__ __forceinline__ void unpack2(unsigned long long v, float& x, float& y) {
    asm("mov.b64 {%0, %1}, %2;" : "=f"(x), "=f"(y) : "l"(v));
}

// ---------------- prep: build transposed/concatenated weights ----------------
__global__ void prep_kernel(const float* __restrict__ w_enc,
                            const float* __restrict__ w_loc) {
    int idx = blockIdx.x * blockDim.x + threadIdx.x;
    if (idx >= ETOT * AA) return;
    int row = idx / AA;
    int a   = idx % AA;
    float v = (row < DENC) ? w_enc[a * DENC + row]
                           : w_loc[a * NFF + (row - DENC)];
    g_wT[idx] = v;
}

// ---------------- mel projection: [B,A] = mel @ w_in^T + b ----------------
__global__ void melproj_kernel(const float* __restrict__ mel,
                               const float* __restrict__ w_in,
                               const float* __restrict__ b_in) {
    __shared__ float ms[DDEC];
    int b = blockIdx.x;
    int a = threadIdx.x;               // 512 threads
    ms[a]       = mel[b * DDEC + a];
    ms[a + 512] = mel[b * DDEC + a + 512];
    __syncthreads();
    float acc = b_in[a];
    const float4* wr = (const float4*)(w_in + (size_t)a * DDEC);
#pragma unroll 8
    for (int e = 0; e < DDEC / 4; ++e) {
        float4 w = wr[e];
        float4 m = *(const float4*)&ms[e * 4];
        acc += w.x * m.x + w.y * m.y + w.z * m.z + w.w * m.w;
    }
    g_mel[b * AA + a] = acc;
}

// ---------------- conv1d(2->32, K=31, SAME) -> locfeat[b][t][f] ----------------
__global__ void conv_kernel(const float* __restrict__ cum,
                            const float* __restrict__ conv_w) {
    __shared__ float ch[2][TT_ + 32];
    __shared__ float cw[NFF][2][KK + 1];
    int b = blockIdx.x;
    int tid = threadIdx.x;             // 256
    for (int i = tid; i < TT_ + 32; i += 256) {
        float v0 = 0.f, v1 = 0.f;
        int t = i - 15;                // pad 15 on each side
        if (t >= 0 && t < TT_) {
            v0 = cum[b * 2 * TT_ + t];
            v1 = cum[b * 2 * TT_ + TT_ + t];
        }
        ch[0][i] = v0; ch[1][i] = v1;
    }
    for (int i = tid; i < NFF * 2 * KK; i += 256) {
        int f = i / (2 * KK);
        int r = i % (2 * KK);
        cw[f][r / KK][r % KK] = conv_w[i];
    }
    __syncthreads();
    for (int idx = tid; idx < TT_ * NFF; idx += 256) {
        int t = idx >> 5;
        int f = idx & 31;
        float acc = 0.f;
#pragma unroll
        for (int k = 0; k < KK; ++k)
            acc += ch[0][t + k] * cw[f][0][k] + ch[1][t + k] * cw[f][1][k];
        g_locfeat[((size_t)b * TT_ + t) * NFF + f] = acc;
    }
}

// ---------------- fused energy GEMM: energies[b][t] ----------------
// block = (t-tile of 32, b). 256 threads. warp w owns a-cols [w*64, w*64+64).
// thread tile: 8 t x 8 a, accumulated as fp32x2 pairs (FFMA2).
__global__ void __launch_bounds__(256, 2) energy_kernel(
        const float* __restrict__ enc,
        const int* __restrict__ mask,
        const float* __restrict__ w_energy) {
    __shared__ float w_s[16][AA];      // 32 KB weight chunk, row = feature e
    __shared__ float f_s[16][36];      // features f_s[e][t], padded stride
    __shared__ float mel_s[AA];
    __shared__ float weng_s[AA];
    __shared__ float red_s[8][32];

    int b  = blockIdx.y;
    int t0 = blockIdx.x * 32;
    int tid  = threadIdx.x;
    int warp = tid >> 5, lane = tid & 31;
    int ag = lane & 7, tg = lane >> 3;
    int abase = warp * 64 + ag * 8;
    int tbase = tg * 8;

    mel_s[tid]        = g_mel[b * AA + tid];
    mel_s[tid + 256]  = g_mel[b * AA + tid + 256];
    weng_s[tid]       = w_energy[tid];
    weng_s[tid + 256] = w_energy[tid + 256];
    __syncthreads();

    unsigned long long acc[8][4];
#pragma unroll
    for (int jp = 0; jp < 4; ++jp) {
        unsigned long long m = pack2(mel_s[abase + 2 * jp], mel_s[abase + 2 * jp + 1]);
#pragma unroll
        for (int i = 0; i < 8; ++i) acc[i][jp] = m;
    }

    int tldr = tid >> 3;               // 0..31
    int e2   = (tid & 7) * 2;          // 0..14
    const float* encb = enc + ((size_t)b * TT_ + t0) * DENC;
    const float* locb = g_locfeat + ((size_t)b * TT_ + t0) * NFF;

    for (int c = 0; c < 34; ++c) {     // 32 enc chunks + 2 loc chunks of 16 features
        __syncthreads();
        const float4* wsrc = (const float4*)(g_wT + (size_t)c * 16 * AA);
        float4* wdst = (float4*)&w_s[0][0];
#pragma unroll
        for (int k = 0; k < 8; ++k) wdst[tid + k * 256] = wsrc[tid + k * 256];
        float2 v;
        if (c < 32) v = *(const float2*)(encb + (size_t)tldr * DENC + c * 16 + e2);
        else        v = *(const float2*)(locb + (size_t)tldr * NFF + (c - 32) * 16 + e2);
        f_s[e2][tldr]     = v.x;
        f_s[e2 + 1][tldr] = v.y;
        __syncthreads();

#pragma unroll
        for (int e = 0; e < 16; ++e) {
            const unsigned long long* wrow = (const unsigned long long*)&w_s[e][abase];
            unsigned long long w0 = wrow[0], w1 = wrow[1], w2 = wrow[2], w3 = wrow[3];
            const float4* frow = (const float4*)&f_s[e][tbase];
            float4 fa = frow[0], fb = frow[1];
            float fv[8] = {fa.x, fa.y, fa.z, fa.w, fb.x, fb.y, fb.z, fb.w};
#pragma unroll
            for (int i = 0; i < 8; ++i) {
                unsigned long long ed = pack2(fv[i], fv[i]);
                acc[i][0] = fma2(ed, w0, acc[i][0]);
                acc[i][1] = fma2(ed, w1, acc[i][1]);
                acc[i][2] = fma2(ed, w2, acc[i][2]);
                acc[i][3] = fma2(ed, w3, acc[i][3]);
            }
        }
    }

    // epilogue: energy[t] = sum_a w_energy[a] * tanh(acc[t][a])
#pragma unroll
    for (int i = 0; i < 8; ++i) {
        float s = 0.f;
#pragma unroll
        for (int jp = 0; jp < 4; ++jp) {
            float lo, hi;
            unpack2(acc[i][jp], lo, hi);
            s += tanhf(lo) * weng_s[abase + 2 * jp]
               + tanhf(hi) * weng_s[abase + 2 * jp + 1];
        }
        s += __shfl_xor_sync(0xffffffffu, s, 1);
        s += __shfl_xor_sync(0xffffffffu, s, 2);
        s += __shfl_xor_sync(0xffffffffu, s, 4);
        if (ag == 0) red_s[warp][tbase + i] = s;
    }
    __syncthreads();
    if (tid < 32) {
        float en = 0.f;
#pragma unroll
        for (int w = 0; w < 8; ++w) en += red_s[w][tid];
        int gt = t0 + tid;
        // mask may be int32 0/1 or float32 0.0/1.0 — nonzero bits == masked either way
        g_energy[b * TT_ + gt] = (mask[b * TT_ + gt] != 0) ? -INFINITY : en;
    }
}

// ---------------- softmax over T, writes weights to out[B*DENC ...] ----------------
__global__ void softmax_kernel(float* __restrict__ out) {
    __shared__ float red[256];
    int b = blockIdx.x, tid = threadIdx.x;
    const float* eng = g_energy + b * TT_;
    float x[4];
    float m = -INFINITY;
#pragma unroll
    for (int j = 0; j < 4; ++j) { x[j] = eng[tid + j * 256]; m = fmaxf(m, x[j]); }
    red[tid] = m; __syncthreads();
    for (int s = 128; s > 0; s >>= 1) {
        if (tid < s) red[tid] = fmaxf(red[tid], red[tid + s]);
        __syncthreads();
    }
    m = red[0]; __syncthreads();
    float sum = 0.f;
#pragma unroll
    for (int j = 0; j < 4; ++j) { x[j] = expf(x[j] - m); sum += x[j]; }
    red[tid] = sum; __syncthreads();
    for (int s = 128; s > 0; s >>= 1) {
        if (tid < s) red[tid] += red[tid + s];
        __syncthreads();
    }
    float inv = 1.0f / red[0];
    float* wout = out + BB * DENC + b * TT_;
#pragma unroll
    for (int j = 0; j < 4; ++j) wout[tid + j * 256] = x[j] * inv;
}

// ---------------- context = sum_t w[t] * enc[b][t][:], split over 8 t-chunks ----------------
__global__ void ctx_part_kernel(const float* __restrict__ enc,
                                const float* __restrict__ out) {
    __shared__ float ws[128];
    int b = blockIdx.y, ck = blockIdx.x, tid = threadIdx.x;  // 256 threads
    int t0 = ck * 128;
    if (tid < 128) ws[tid] = out[BB * DENC + b * TT_ + t0 + tid];
    __syncthreads();
    int e = tid * 2;
    float2 acc = make_float2(0.f, 0.f);
    const float* ep = enc + ((size_t)b * TT_ + t0) * DENC + e;
#pragma unroll 4
    for (int t = 0; t < 128; ++t) {
        float2 v = *(const float2*)(ep + (size_t)t * DENC);
        acc.x += ws[t] * v.x;
        acc.y += ws[t] * v.y;
    }
    *(float2*)&g_ctxp[((size_t)ck * BB + b) * DENC + e] = acc;
}

__global__ void ctx_reduce_kernel(float* __restrict__ out) {
    int b = blockIdx.x, e = threadIdx.x;   // 512 threads
    float s = 0.f;
#pragma unroll
    for (int c = 0; c < 8; ++c) s += g_ctxp[((size_t)c * BB + b) * DENC + e];
    out[b * DENC + e] = s;
}

// ---------------- launch ----------------
extern "C" void kernel_launch(void* const* d_in, const int* in_sizes, int n_in,
                              void* d_out, int out_size) {
    const float* mel      = (const float*)d_in[0];
    const float* enc      = (const float*)d_in[1];
    const float* cum      = (const float*)d_in[2];
    const int*   mask     = (const int*)d_in[3];
    const float* w_in     = (const float*)d_in[4];
    const float* b_in     = (const float*)d_in[5];
    const float* w_enc    = (const float*)d_in[6];
    const float* conv_w   = (const float*)d_in[7];
    const float* w_loc    = (const float*)d_in[8];
    const float* w_energy = (const float*)d_in[9];
    float* out = (float*)d_out;

    prep_kernel<<<(ETOT * AA + 255) / 256, 256>>>(w_enc, w_loc);
    melproj_kernel<<<BB, 512>>>(mel, w_in, b_in);
    conv_kernel<<<BB, 256>>>(cum, conv_w);
    dim3 ge(32, BB);
    energy_kernel<<<ge, 256>>>(enc, mask, w_energy);
    softmax_kernel<<<BB, 256>>>(out);
    dim3 gc(8, BB);
    ctx_part_kernel<<<gc, 256>>>(enc, out);
    ctx_reduce_kernel<<<BB, 512>>>(out);
}

// round 5
// speedup vs baseline: 2.1040x; 2.1040x over previous
#include <cuda_runtime.h>
#include <cuda_bf16.h>
#include <stdint.h>
#include <math.h>

#define BB   64
#define TT_  1024
#define DDEC 1024
#define DENC 512
#define AA   512
#define NFF  32
#define KK   31
#define KPAD 576
#define STAGE_BYTES 98304      /* Ahi 16K | Alo 16K | Bhi 32K | Blo 32K */
#define SMEM_DYN (2 * STAGE_BYTES)

#define SW(o) ((o) ^ (((o) >> 3) & 0x70))

// ---------------- device scratch ----------------
__device__ __nv_bfloat16 g_enc_hi[BB * TT_ * KPAD];
__device__ __nv_bfloat16 g_enc_lo[BB * TT_ * KPAD];
__device__ __nv_bfloat16 g_w_hi[AA * KPAD];
__device__ __nv_bfloat16 g_w_lo[AA * KPAD];
__device__ float g_locfeat[BB * TT_ * NFF];
__device__ float g_mel[BB * AA];
__device__ float g_energy[BB * TT_];
__device__ float g_ctxp[8 * BB * DENC];

// ---------------- helpers ----------------
__device__ __forceinline__ uint32_t smem_u32(const void* p) {
    uint32_t a;
    asm("{ .reg .u64 t; cvta.to.shared.u64 t, %1; cvt.u32.u64 %0, t; }" : "=r"(a) : "l"(p));
    return a;
}
__device__ __forceinline__ void cp16(uint32_t dst, const void* src) {
    asm volatile("cp.async.cg.shared.global [%0], [%1], 16;" :: "r"(dst), "l"(src));
}
#define CP_COMMIT() asm volatile("cp.async.commit_group;" ::: "memory")
#define CP_WAIT1()  asm volatile("cp.async.wait_group 1;" ::: "memory")
#define CP_WAIT0()  asm volatile("cp.async.wait_group 0;" ::: "memory")

__device__ __forceinline__ void ldmx4(uint32_t* r, uint32_t addr) {
    asm volatile("ldmatrix.sync.aligned.m8n8.x4.shared.b16 {%0,%1,%2,%3}, [%4];"
                 : "=r"(r[0]), "=r"(r[1]), "=r"(r[2]), "=r"(r[3]) : "r"(addr));
}
__device__ __forceinline__ void ldmx2(uint32_t* r, uint32_t addr) {
    asm volatile("ldmatrix.sync.aligned.m8n8.x2.shared.b16 {%0,%1}, [%2];"
                 : "=r"(r[0]), "=r"(r[1]) : "r"(addr));
}
__device__ __forceinline__ void mma16816(float* d, const uint32_t* a, const uint32_t* b) {
    asm volatile("mma.sync.aligned.m16n8k16.row.col.f32.bf16.bf16.f32 "
                 "{%0,%1,%2,%3}, {%4,%5,%6,%7}, {%8,%9}, {%0,%1,%2,%3};"
                 : "+f"(d[0]), "+f"(d[1]), "+f"(d[2]), "+f"(d[3])
                 : "r"(a[0]), "r"(a[1]), "r"(a[2]), "r"(a[3]), "r"(b[0]), "r"(b[1]));
}
__device__ __forceinline__ void cvt_hilo(float x, unsigned short& hi, unsigned short& lo) {
    __nv_bfloat16 h = __float2bfloat16(x);
    float r = x - __bfloat162float(h);
    __nv_bfloat16 l = __float2bfloat16(r);
    hi = *reinterpret_cast<unsigned short*>(&h);
    lo = *reinterpret_cast<unsigned short*>(&l);
}
__device__ __forceinline__ float fast_tanh(float x) {
    x = fminf(fmaxf(x, -15.f), 15.f);
    float t = __expf(2.f * x);
    return __fdividef(t - 1.f, t + 1.f);
}

// ---------------- prep: fp32 -> bf16 hi/lo, K padded to 576 ----------------
// enc rows: k<512 from enc, 512..543 from locfeat, rest zero
__global__ void prep_enc_kernel(const float* __restrict__ enc) {
    int row = blockIdx.x;          // 0..65535
    int k4  = threadIdx.x;         // 0..143
    float4 v = make_float4(0.f, 0.f, 0.f, 0.f);
    if (k4 < 128)       v = *(const float4*)(enc + (size_t)row * DENC + k4 * 4);
    else if (k4 < 136)  v = *(const float4*)(g_locfeat + (size_t)row * NFF + (k4 - 128) * 4);
    unsigned short h0, l0, h1, l1, h2, l2, h3, l3;
    cvt_hilo(v.x, h0, l0); cvt_hilo(v.y, h1, l1);
    cvt_hilo(v.z, h2, l2); cvt_hilo(v.w, h3, l3);
    size_t o = (size_t)row * KPAD + k4 * 4;
    *(uint2*)(g_enc_hi + o) = make_uint2((uint32_t)h0 | ((uint32_t)h1 << 16),
                                         (uint32_t)h2 | ((uint32_t)h3 << 16));
    *(uint2*)(g_enc_lo + o) = make_uint2((uint32_t)l0 | ((uint32_t)l1 << 16),
                                         (uint32_t)l2 | ((uint32_t)l3 << 16));
}

__global__ void prep_w_kernel(const float* __restrict__ w_enc,
                              const float* __restrict__ w_loc) {
    int a  = blockIdx.x;           // 0..511
    int k4 = threadIdx.x;          // 0..143
    float4 v = make_float4(0.f, 0.f, 0.f, 0.f);
    if (k4 < 128)       v = *(const float4*)(w_enc + (size_t)a * DENC + k4 * 4);
    else if (k4 < 136)  v = *(const float4*)(w_loc + (size_t)a * NFF + (k4 - 128) * 4);
    unsigned short h0, l0, h1, l1, h2, l2, h3, l3;
    cvt_hilo(v.x, h0, l0); cvt_hilo(v.y, h1, l1);
    cvt_hilo(v.z, h2, l2); cvt_hilo(v.w, h3, l3);
    size_t o = (size_t)a * KPAD + k4 * 4;
    *(uint2*)(g_w_hi + o) = make_uint2((uint32_t)h0 | ((uint32_t)h1 << 16),
                                       (uint32_t)h2 | ((uint32_t)h3 << 16));
    *(uint2*)(g_w_lo + o) = make_uint2((uint32_t)l0 | ((uint32_t)l1 << 16),
                                       (uint32_t)l2 | ((uint32_t)l3 << 16));
}

// ---------------- mel projection ----------------
__global__ void melproj_kernel(const float* __restrict__ mel,
                               const float* __restrict__ w_in,
                               const float* __restrict__ b_in) {
    __shared__ float ms[DDEC];
    int b = blockIdx.x;
    int a = threadIdx.x;
    ms[a]       = mel[b * DDEC + a];
    ms[a + 512] = mel[b * DDEC + a + 512];
    __syncthreads();
    float acc = b_in[a];
    const float4* wr = (const float4*)(w_in + (size_t)a * DDEC);
#pragma unroll 8
    for (int e = 0; e < DDEC / 4; ++e) {
        float4 w = wr[e];
        float4 m = *(const float4*)&ms[e * 4];
        acc += w.x * m.x + w.y * m.y + w.z * m.z + w.w * m.w;
    }
    g_mel[b * AA + a] = acc;
}

// ---------------- conv1d(2->32, K=31, SAME) ----------------
__global__ void conv_kernel(const float* __restrict__ cum,
                            const float* __restrict__ conv_w) {
    __shared__ float ch[2][TT_ + 32];
    __shared__ float cw[NFF][2][KK + 1];
    int b = blockIdx.x;
    int tid = threadIdx.x;
    for (int i = tid; i < TT_ + 32; i += 256) {
        float v0 = 0.f, v1 = 0.f;
        int t = i - 15;
        if (t >= 0 && t < TT_) {
            v0 = cum[b * 2 * TT_ + t];
            v1 = cum[b * 2 * TT_ + TT_ + t];
        }
        ch[0][i] = v0; ch[1][i] = v1;
    }
    for (int i = tid; i < NFF * 2 * KK; i += 256) {
        int f = i / (2 * KK);
        int r = i % (2 * KK);
        cw[f][r / KK][r % KK] = conv_w[i];
    }
    __syncthreads();
    for (int idx = tid; idx < TT_ * NFF; idx += 256) {
        int t = idx >> 5;
        int f = idx & 31;
        float acc = 0.f;
#pragma unroll
        for (int k = 0; k < KK; ++k)
            acc += ch[0][t + k] * cw[f][0][k] + ch[1][t + k] * cw[f][1][k];
        g_locfeat[((size_t)b * TT_ + t) * NFF + f] = acc;
    }
}

// ---------------- HMMA energy GEMM ----------------
// CTA: 128 t-rows, full N=512 in 2 passes of 256. 8 warps; warp owns 32 n-cols.
// K streamed in 9 chunks of 64 via cp.async double buffer.
__device__ __forceinline__ void stage_issue(uint32_t sbase,
        const __nv_bfloat16* ehi, const __nv_bfloat16* elo,
        const __nv_bfloat16* whi, const __nv_bfloat16* wlo,
        int kc, int tid) {
#pragma unroll
    for (int j = 0; j < 4; ++j) {          // A: 128 rows x 128B
        int sg = tid + j * 256;
        int row = sg >> 3, s16 = sg & 7;
        uint32_t dst = sbase + SW(row * 128 + s16 * 16);
        size_t so = (size_t)row * KPAD + kc * 64 + s16 * 8;
        cp16(dst,         ehi + so);
        cp16(dst + 16384, elo + so);
    }
#pragma unroll
    for (int j = 0; j < 8; ++j) {          // B: 256 rows x 128B
        int sg = tid + j * 256;
        int row = sg >> 3, s16 = sg & 7;
        uint32_t dst = sbase + 32768 + SW(row * 128 + s16 * 16);
        size_t so = (size_t)row * KPAD + kc * 64 + s16 * 8;
        cp16(dst,         whi + so);
        cp16(dst + 32768, wlo + so);
    }
}

__global__ void __launch_bounds__(256, 1)
gemm_energy_kernel(const float* __restrict__ w_energy) {
    extern __shared__ char dsm[];
    __shared__ float mel_s[AA];
    __shared__ float weng_s[AA];
    __shared__ float red_s[8 * 128];

    uint32_t sdyn = smem_u32(dsm);
    int tid = threadIdx.x, w = tid >> 5, lane = tid & 31;
    int tile = blockIdx.x;                     // 0..511
    int brow0 = tile * 128;                    // global (b*T + t) row base
    int b = brow0 >> 10;

    mel_s[tid]        = g_mel[b * AA + tid];
    mel_s[tid + 256]  = g_mel[b * AA + tid + 256];
    weng_s[tid]       = w_energy[tid];
    weng_s[tid + 256] = w_energy[tid + 256];
    __syncthreads();

    const __nv_bfloat16* ehi = g_enc_hi + (size_t)brow0 * KPAD;
    const __nv_bfloat16* elo = g_enc_lo + (size_t)brow0 * KPAD;

    float epart[8][2];
#pragma unroll
    for (int mt = 0; mt < 8; ++mt) { epart[mt][0] = 0.f; epart[mt][1] = 0.f; }

    for (int pass = 0; pass < 2; ++pass) {
        const __nv_bfloat16* whi = g_w_hi + (size_t)(pass * 256) * KPAD;
        const __nv_bfloat16* wlo = g_w_lo + (size_t)(pass * 256) * KPAD;

        float acc[8][4][4];
#pragma unroll
        for (int mt = 0; mt < 8; ++mt)
#pragma unroll
            for (int nt = 0; nt < 4; ++nt)
#pragma unroll
                for (int r = 0; r < 4; ++r) acc[mt][nt][r] = 0.f;

        stage_issue(sdyn, ehi, elo, whi, wlo, 0, tid);
        CP_COMMIT();

        for (int kc = 0; kc < 9; ++kc) {
            if (kc < 8) {
                stage_issue(sdyn + ((kc + 1) & 1) * STAGE_BYTES, ehi, elo, whi, wlo, kc + 1, tid);
                CP_COMMIT();
                CP_WAIT1();
            } else {
                CP_WAIT0();
            }
            __syncthreads();
            uint32_t sa = sdyn + (kc & 1) * STAGE_BYTES;
            int nks = (kc == 8) ? 2 : 4;
            for (int ks = 0; ks < nks; ++ks) {
                uint32_t bh[4][2], bl[4][2];
#pragma unroll
                for (int nt = 0; nt < 4; ++nt) {
                    int brow = w * 32 + nt * 8 + (lane & 7);
                    uint32_t boff = SW(brow * 128 + ks * 32 + ((lane >> 3) & 1) * 16);
                    ldmx2(bh[nt], sa + 32768 + boff);
                    ldmx2(bl[nt], sa + 65536 + boff);
                }
#pragma unroll
                for (int mt = 0; mt < 8; ++mt) {
                    int arow = mt * 16 + (lane & 15);
                    uint32_t aoff = SW(arow * 128 + ks * 32 + ((lane >> 4) & 1) * 16);
                    uint32_t ah[4], al[4];
                    ldmx4(ah, sa + aoff);
                    ldmx4(al, sa + 16384 + aoff);
#pragma unroll
                    for (int nt = 0; nt < 4; ++nt) {
                        mma16816(acc[mt][nt], ah, bh[nt]);
                        mma16816(acc[mt][nt], ah, bl[nt]);
                        mma16816(acc[mt][nt], al, bh[nt]);
                    }
                }
            }
            __syncthreads();
        }

        // per-pass epilogue: tanh(+mel) * weng, accumulate row partials
#pragma unroll
        for (int mt = 0; mt < 8; ++mt)
#pragma unroll
            for (int nt = 0; nt < 4; ++nt) {
                int n = pass * 256 + w * 32 + nt * 8 + (lane & 3) * 2;
                epart[mt][0] += fast_tanh(acc[mt][nt][0] + mel_s[n]) * weng_s[n]
                              + fast_tanh(acc[mt][nt][1] + mel_s[n + 1]) * weng_s[n + 1];
                epart[mt][1] += fast_tanh(acc[mt][nt][2] + mel_s[n]) * weng_s[n]
                              + fast_tanh(acc[mt][nt][3] + mel_s[n + 1]) * weng_s[n + 1];
            }
    }

    // cross-lane + cross-warp reduction
#pragma unroll
    for (int mt = 0; mt < 8; ++mt)
#pragma unroll
        for (int h = 0; h < 2; ++h) {
            float s = epart[mt][h];
            s += __shfl_xor_sync(0xffffffffu, s, 1);
            s += __shfl_xor_sync(0xffffffffu, s, 2);
            if ((lane & 3) == 0)
                red_s[w * 128 + mt * 16 + h * 8 + (lane >> 2)] = s;
        }
    __syncthreads();
    if (tid < 128) {
        float e = 0.f;
#pragma unroll
        for (int w2 = 0; w2 < 8; ++w2) e += red_s[w2 * 128 + tid];
        g_energy[brow0 + tid] = e;
    }
}

// ---------------- softmax (applies mask), writes weights to out ----------------
__global__ void softmax_kernel(const int* __restrict__ mask, float* __restrict__ out) {
    __shared__ float red[256];
    int b = blockIdx.x, tid = threadIdx.x;
    const float* eng = g_energy + b * TT_;
    const int*   mk  = mask + b * TT_;
    float x[4];
    float m = -INFINITY;
#pragma unroll
    for (int j = 0; j < 4; ++j) {
        int t = tid + j * 256;
        x[j] = (mk[t] != 0) ? -INFINITY : eng[t];
        m = fmaxf(m, x[j]);
    }
    red[tid] = m; __syncthreads();
    for (int s = 128; s > 0; s >>= 1) {
        if (tid < s) red[tid] = fmaxf(red[tid], red[tid + s]);
        __syncthreads();
    }
    m = red[0]; __syncthreads();
    float sum = 0.f;
#pragma unroll
    for (int j = 0; j < 4; ++j) { x[j] = expf(x[j] - m); sum += x[j]; }
    red[tid] = sum; __syncthreads();
    for (int s = 128; s > 0; s >>= 1) {
        if (tid < s) red[tid] += red[tid + s];
        __syncthreads();
    }
    float inv = 1.0f / red[0];
    float* wout = out + BB * DENC + b * TT_;
#pragma unroll
    for (int j = 0; j < 4; ++j) wout[tid + j * 256] = x[j] * inv;
}

// ---------------- context ----------------
__global__ void ctx_part_kernel(const float* __restrict__ enc,
                                const float* __restrict__ out) {
    __shared__ float ws[128];
    int b = blockIdx.y, ck = blockIdx.x, tid = threadIdx.x;
    int t0 = ck * 128;
    if (tid < 128) ws[tid] = out[BB * DENC + b * TT_ + t0 + tid];
    __syncthreads();
    int e = tid * 2;
    float2 acc = make_float2(0.f, 0.f);
    const float* ep = enc + ((size_t)b * TT_ + t0) * DENC + e;
#pragma unroll 4
    for (int t = 0; t < 128; ++t) {
        float2 v = *(const float2*)(ep + (size_t)t * DENC);
        acc.x += ws[t] * v.x;
        acc.y += ws[t] * v.y;
    }
    *(float2*)&g_ctxp[((size_t)ck * BB + b) * DENC + e] = acc;
}

__global__ void ctx_reduce_kernel(float* __restrict__ out) {
    int b = blockIdx.x, e = threadIdx.x;
    float s = 0.f;
#pragma unroll
    for (int c = 0; c < 8; ++c) s += g_ctxp[((size_t)c * BB + b) * DENC + e];
    out[b * DENC + e] = s;
}

// ---------------- launch ----------------
extern "C" void kernel_launch(void* const* d_in, const int* in_sizes, int n_in,
                              void* d_out, int out_size) {
    const float* mel      = (const float*)d_in[0];
    const float* enc      = (const float*)d_in[1];
    const float* cum      = (const float*)d_in[2];
    const int*   mask     = (const int*)d_in[3];
    const float* w_in     = (const float*)d_in[4];
    const float* b_in     = (const float*)d_in[5];
    const float* w_enc    = (const float*)d_in[6];
    const float* conv_w   = (const float*)d_in[7];
    const float* w_loc    = (const float*)d_in[8];
    const float* w_energy = (const float*)d_in[9];
    float* out = (float*)d_out;

    cudaFuncSetAttribute(gemm_energy_kernel,
                         cudaFuncAttributeMaxDynamicSharedMemorySize, SMEM_DYN);

    conv_kernel<<<BB, 256>>>(cum, conv_w);
    melproj_kernel<<<BB, 512>>>(mel, w_in, b_in);
    prep_w_kernel<<<AA, 144>>>(w_enc, w_loc);
    prep_enc_kernel<<<BB * TT_, 144>>>(enc);
    gemm_energy_kernel<<<512, 256, SMEM_DYN>>>(w_energy);
    softmax_kernel<<<BB, 256>>>(mask, out);
    dim3 gc(8, BB);
    ctx_part_kernel<<<gc, 256>>>(enc, out);
    ctx_reduce_kernel<<<BB, 512>>>(out);
}

// round 6
// speedup vs baseline: 2.1469x; 1.0204x over previous
#include <cuda_runtime.h>
#include <cuda_bf16.h>
#include <stdint.h>
#include <math.h>

#define BB   64
#define TT_  1024
#define DDEC 1024
#define DENC 512
#define AA   512
#define NFF  32
#define KK   31
#define KPAD 576
#define STAGE_BYTES 98304      /* Ahi 16K | Alo 16K | Bhi 32K | Blo 32K */
#define SMEM_DYN (2 * STAGE_BYTES)

#define SW(o) ((o) ^ (((o) >> 3) & 0x70))

// ---------------- device scratch ----------------
__device__ __nv_bfloat16 g_w_hi[AA * KPAD];
__device__ __nv_bfloat16 g_w_lo[AA * KPAD];
__device__ float g_locfeat[BB * TT_ * NFF];
__device__ float g_mel[BB * AA];
__device__ float g_energy[BB * TT_];
__device__ float g_ctxp[8 * BB * DENC];

// ---------------- helpers ----------------
__device__ __forceinline__ uint32_t smem_u32(const void* p) {
    uint32_t a;
    asm("{ .reg .u64 t; cvta.to.shared.u64 t, %1; cvt.u32.u64 %0, t; }" : "=r"(a) : "l"(p));
    return a;
}
__device__ __forceinline__ void cp16(uint32_t dst, const void* src) {
    asm volatile("cp.async.cg.shared.global [%0], [%1], 16;" :: "r"(dst), "l"(src));
}
#define CP_COMMIT() asm volatile("cp.async.commit_group;" ::: "memory")
#define CP_WAIT1()  asm volatile("cp.async.wait_group 1;" ::: "memory")
#define CP_WAIT0()  asm volatile("cp.async.wait_group 0;" ::: "memory")

__device__ __forceinline__ void ldmx4(uint32_t* r, uint32_t addr) {
    asm volatile("ldmatrix.sync.aligned.m8n8.x4.shared.b16 {%0,%1,%2,%3}, [%4];"
                 : "=r"(r[0]), "=r"(r[1]), "=r"(r[2]), "=r"(r[3]) : "r"(addr));
}
__device__ __forceinline__ void ldmx2(uint32_t* r, uint32_t addr) {
    asm volatile("ldmatrix.sync.aligned.m8n8.x2.shared.b16 {%0,%1}, [%2];"
                 : "=r"(r[0]), "=r"(r[1]) : "r"(addr));
}
__device__ __forceinline__ void mma16816(float* d, const uint32_t* a, const uint32_t* b) {
    asm volatile("mma.sync.aligned.m16n8k16.row.col.f32.bf16.bf16.f32 "
                 "{%0,%1,%2,%3}, {%4,%5,%6,%7}, {%8,%9}, {%0,%1,%2,%3};"
                 : "+f"(d[0]), "+f"(d[1]), "+f"(d[2]), "+f"(d[3])
                 : "r"(a[0]), "r"(a[1]), "r"(a[2]), "r"(a[3]), "r"(b[0]), "r"(b[1]));
}
__device__ __forceinline__ void cvt_hilo(float x, unsigned short& hi, unsigned short& lo) {
    __nv_bfloat16 h = __float2bfloat16(x);
    float r = x - __bfloat162float(h);
    __nv_bfloat16 l = __float2bfloat16(r);
    hi = *reinterpret_cast<unsigned short*>(&h);
    lo = *reinterpret_cast<unsigned short*>(&l);
}
__device__ __forceinline__ float fast_tanh(float x) {
    x = fminf(fmaxf(x, -15.f), 15.f);
    float t = __expf(2.f * x);
    return __fdividef(t - 1.f, t + 1.f);
}

// ---------------- prep: weights fp32 -> bf16 hi/lo, K padded to 576 ----------------
__global__ void prep_w_kernel(const float* __restrict__ w_enc,
                              const float* __restrict__ w_loc) {
    int a  = blockIdx.x;           // 0..511
    int k4 = threadIdx.x;          // 0..143
    float4 v = make_float4(0.f, 0.f, 0.f, 0.f);
    if (k4 < 128)       v = *(const float4*)(w_enc + (size_t)a * DDEC / 2 + k4 * 4);
    else if (k4 < 136)  v = *(const float4*)(w_loc + (size_t)a * NFF + (k4 - 128) * 4);
    unsigned short h0, l0, h1, l1, h2, l2, h3, l3;
    cvt_hilo(v.x, h0, l0); cvt_hilo(v.y, h1, l1);
    cvt_hilo(v.z, h2, l2); cvt_hilo(v.w, h3, l3);
    size_t o = (size_t)a * KPAD + k4 * 4;
    *(uint2*)(g_w_hi + o) = make_uint2((uint32_t)h0 | ((uint32_t)h1 << 16),
                                       (uint32_t)h2 | ((uint32_t)h3 << 16));
    *(uint2*)(g_w_lo + o) = make_uint2((uint32_t)l0 | ((uint32_t)l1 << 16),
                                       (uint32_t)l2 | ((uint32_t)l3 << 16));
}

// ---------------- mel projection ----------------
__global__ void melproj_kernel(const float* __restrict__ mel,
                               const float* __restrict__ w_in,
                               const float* __restrict__ b_in) {
    __shared__ float ms[DDEC];
    int b = blockIdx.x;
    int a = threadIdx.x;
    ms[a]       = mel[b * DDEC + a];
    ms[a + 512] = mel[b * DDEC + a + 512];
    __syncthreads();
    float acc = b_in[a];
    const float4* wr = (const float4*)(w_in + (size_t)a * DDEC);
#pragma unroll 8
    for (int e = 0; e < DDEC / 4; ++e) {
        float4 w = wr[e];
        float4 m = *(const float4*)&ms[e * 4];
        acc += w.x * m.x + w.y * m.y + w.z * m.z + w.w * m.w;
    }
    g_mel[b * AA + a] = acc;
}

// ---------------- conv1d(2->32, K=31, SAME) ----------------
__global__ void conv_kernel(const float* __restrict__ cum,
                            const float* __restrict__ conv_w) {
    __shared__ float ch[2][TT_ + 32];
    __shared__ float cw[NFF][2][KK + 1];
    int b = blockIdx.x;
    int tid = threadIdx.x;
    for (int i = tid; i < TT_ + 32; i += 256) {
        float v0 = 0.f, v1 = 0.f;
        int t = i - 15;
        if (t >= 0 && t < TT_) {
            v0 = cum[b * 2 * TT_ + t];
            v1 = cum[b * 2 * TT_ + TT_ + t];
        }
        ch[0][i] = v0; ch[1][i] = v1;
    }
    for (int i = tid; i < NFF * 2 * KK; i += 256) {
        int f = i / (2 * KK);
        int r = i % (2 * KK);
        cw[f][r / KK][r % KK] = conv_w[i];
    }
    __syncthreads();
    for (int idx = tid; idx < TT_ * NFF; idx += 256) {
        int t = idx >> 5;
        int f = idx & 31;
        float acc = 0.f;
#pragma unroll
        for (int k = 0; k < KK; ++k)
            acc += ch[0][t + k] * cw[f][0][k] + ch[1][t + k] * cw[f][1][k];
        g_locfeat[((size_t)b * TT_ + t) * NFF + f] = acc;
    }
}

// ---------------- HMMA energy GEMM with fused fp32->bf16 hi/lo A conversion ----
// CTA: 128 t-rows, N=512 in 2 passes of 256. 8 warps; warp owns 32 n-cols.
// A: LDG fp32 -> cvt -> swizzled STS (software pipelined). B: cp.async bf16 pre-split.
__device__ __forceinline__ void ldgA(float4* r, const float* __restrict__ enc,
                                     size_t brow0, int kc, int tid) {
#pragma unroll
    for (int j = 0; j < 8; ++j) {
        int g   = tid + j * 256;
        int row = g >> 4, c4 = g & 15;
        if (kc < 8)       r[j] = *(const float4*)(enc + (brow0 + row) * DENC + kc * 64 + c4 * 4);
        else if (c4 < 8)  r[j] = *(const float4*)(g_locfeat + (brow0 + row) * NFF + c4 * 4);
        else              r[j] = make_float4(0.f, 0.f, 0.f, 0.f);
    }
}
__device__ __forceinline__ void stsA(char* stg, const float4* r, int tid) {
#pragma unroll
    for (int j = 0; j < 8; ++j) {
        int g   = tid + j * 256;
        int row = g >> 4, c4 = g & 15;
        unsigned short h0, l0, h1, l1, h2, l2, h3, l3;
        cvt_hilo(r[j].x, h0, l0); cvt_hilo(r[j].y, h1, l1);
        cvt_hilo(r[j].z, h2, l2); cvt_hilo(r[j].w, h3, l3);
        uint32_t sw = SW((uint32_t)(row * 128 + c4 * 8));
        *(uint2*)(stg + sw)         = make_uint2((uint32_t)h0 | ((uint32_t)h1 << 16),
                                                 (uint32_t)h2 | ((uint32_t)h3 << 16));
        *(uint2*)(stg + 16384 + sw) = make_uint2((uint32_t)l0 | ((uint32_t)l1 << 16),
                                                 (uint32_t)l2 | ((uint32_t)l3 << 16));
    }
}
__device__ __forceinline__ void cpB(uint32_t sbase,
        const __nv_bfloat16* __restrict__ whi, const __nv_bfloat16* __restrict__ wlo,
        int kc, int tid) {
#pragma unroll
    for (int j = 0; j < 8; ++j) {
        int sg = tid + j * 256;
        int row = sg >> 3, s16 = sg & 7;
        uint32_t dst = sbase + 32768 + SW(row * 128 + s16 * 16);
        size_t so = (size_t)row * KPAD + kc * 64 + s16 * 8;
        cp16(dst,         whi + so);
        cp16(dst + 32768, wlo + so);
    }
}

__global__ void __launch_bounds__(256, 1)
gemm_energy_kernel(const float* __restrict__ enc,
                   const float* __restrict__ w_energy) {
    extern __shared__ char dsm[];
    __shared__ float mel_s[AA];
    __shared__ float weng_s[AA];
    __shared__ float red_s[8 * 128];

    uint32_t sdyn = smem_u32(dsm);
    int tid = threadIdx.x, w = tid >> 5, lane = tid & 31;
    int tile = blockIdx.x;                     // 0..511
    size_t brow0 = (size_t)tile * 128;         // global (b*T + t) row base
    int b = (int)(brow0 >> 10);

    mel_s[tid]        = g_mel[b * AA + tid];
    mel_s[tid + 256]  = g_mel[b * AA + tid + 256];
    weng_s[tid]       = w_energy[tid];
    weng_s[tid + 256] = w_energy[tid + 256];
    __syncthreads();

    float epart[8][2];
#pragma unroll
    for (int mt = 0; mt < 8; ++mt) { epart[mt][0] = 0.f; epart[mt][1] = 0.f; }

    float4 areg[8];

    for (int pass = 0; pass < 2; ++pass) {
        const __nv_bfloat16* whi = g_w_hi + (size_t)(pass * 256) * KPAD;
        const __nv_bfloat16* wlo = g_w_lo + (size_t)(pass * 256) * KPAD;

        float acc[8][4][4];
#pragma unroll
        for (int mt = 0; mt < 8; ++mt)
#pragma unroll
            for (int nt = 0; nt < 4; ++nt)
#pragma unroll
                for (int r = 0; r < 4; ++r) acc[mt][nt][r] = 0.f;

        // prologue: chunk 0
        ldgA(areg, enc, brow0, 0, tid);
        stsA(dsm, areg, tid);
        cpB(sdyn, whi, wlo, 0, tid);
        CP_COMMIT();

        for (int kc = 0; kc < 9; ++kc) {
            if (kc < 8) {
                ldgA(areg, enc, brow0, kc + 1, tid);       // hidden under MMAs
                cpB(sdyn + ((kc + 1) & 1) * STAGE_BYTES, whi, wlo, kc + 1, tid);
                CP_COMMIT();
                CP_WAIT1();
            } else {
                CP_WAIT0();
            }
            __syncthreads();   // B(kc) arrived; A(kc) STS visible (prev iter / prologue)

            uint32_t sa = sdyn + (kc & 1) * STAGE_BYTES;
            int nks = (kc == 8) ? 2 : 4;
            for (int ks = 0; ks < nks; ++ks) {
                uint32_t bh[4][2], bl[4][2];
#pragma unroll
                for (int nt = 0; nt < 4; ++nt) {
                    int brow = w * 32 + nt * 8 + (lane & 7);
                    uint32_t boff = SW(brow * 128 + ks * 32 + ((lane >> 3) & 1) * 16);
                    ldmx2(bh[nt], sa + 32768 + boff);
                    ldmx2(bl[nt], sa + 65536 + boff);
                }
#pragma unroll
                for (int mt = 0; mt < 8; ++mt) {
                    int arow = mt * 16 + (lane & 15);
                    uint32_t aoff = SW(arow * 128 + ks * 32 + ((lane >> 4) & 1) * 16);
                    uint32_t ah[4], al[4];
                    ldmx4(ah, sa + aoff);
                    ldmx4(al, sa + 16384 + aoff);
#pragma unroll
                    for (int nt = 0; nt < 4; ++nt) {
                        mma16816(acc[mt][nt], ah, bh[nt]);
                        mma16816(acc[mt][nt], ah, bl[nt]);
                        mma16816(acc[mt][nt], al, bh[nt]);
                    }
                }
            }
            if (kc < 8)
                stsA(dsm + ((kc + 1) & 1) * STAGE_BYTES, areg, tid);
            // next iteration's __syncthreads orders STS before ldmatrix
        }
        __syncthreads();       // protect stage 0 from next pass's prologue STS

        // per-pass epilogue: tanh(+mel) * weng, accumulate row partials
#pragma unroll
        for (int mt = 0; mt < 8; ++mt)
#pragma unroll
            for (int nt = 0; nt < 4; ++nt) {
                int n = pass * 256 + w * 32 + nt * 8 + (lane & 3) * 2;
                epart[mt][0] += fast_tanh(acc[mt][nt][0] + mel_s[n]) * weng_s[n]
                              + fast_tanh(acc[mt][nt][1] + mel_s[n + 1]) * weng_s[n + 1];
                epart[mt][1] += fast_tanh(acc[mt][nt][2] + mel_s[n]) * weng_s[n]
                              + fast_tanh(acc[mt][nt][3] + mel_s[n + 1]) * weng_s[n + 1];
            }
    }

    // cross-lane + cross-warp reduction
#pragma unroll
    for (int mt = 0; mt < 8; ++mt)
#pragma unroll
        for (int h = 0; h < 2; ++h) {
            float s = epart[mt][h];
            s += __shfl_xor_sync(0xffffffffu, s, 1);
            s += __shfl_xor_sync(0xffffffffu, s, 2);
            if ((lane & 3) == 0)
                red_s[w * 128 + mt * 16 + h * 8 + (lane >> 2)] = s;
        }
    __syncthreads();
    if (tid < 128) {
        float e = 0.f;
#pragma unroll
        for (int w2 = 0; w2 < 8; ++w2) e += red_s[w2 * 128 + tid];
        g_energy[brow0 + tid] = e;
    }
}

// ---------------- softmax (applies mask), writes weights to out ----------------
__global__ void softmax_kernel(const int* __restrict__ mask, float* __restrict__ out) {
    __shared__ float red[256];
    int b = blockIdx.x, tid = threadIdx.x;
    const float* eng = g_energy + b * TT_;
    const int*   mk  = mask + b * TT_;
    float x[4];
    float m = -INFINITY;
#pragma unroll
    for (int j = 0; j < 4; ++j) {
        int t = tid + j * 256;
        x[j] = (mk[t] != 0) ? -INFINITY : eng[t];
        m = fmaxf(m, x[j]);
    }
    red[tid] = m; __syncthreads();
    for (int s = 128; s > 0; s >>= 1) {
        if (tid < s) red[tid] = fmaxf(red[tid], red[tid + s]);
        __syncthreads();
    }
    m = red[0]; __syncthreads();
    float sum = 0.f;
#pragma unroll
    for (int j = 0; j < 4; ++j) { x[j] = expf(x[j] - m); sum += x[j]; }
    red[tid] = sum; __syncthreads();
    for (int s = 128; s > 0; s >>= 1) {
        if (tid < s) red[tid] += red[tid + s];
        __syncthreads();
    }
    float inv = 1.0f / red[0];
    float* wout = out + BB * DENC + b * TT_;
#pragma unroll
    for (int j = 0; j < 4; ++j) wout[tid + j * 256] = x[j] * inv;
}

// ---------------- context ----------------
__global__ void ctx_part_kernel(const float* __restrict__ enc,
                                const float* __restrict__ out) {
    __shared__ float ws[128];
    int b = blockIdx.y, ck = blockIdx.x, tid = threadIdx.x;
    int t0 = ck * 128;
    if (tid < 128) ws[tid] = out[BB * DENC + b * TT_ + t0 + tid];
    __syncthreads();
    int e = tid * 2;
    float2 acc = make_float2(0.f, 0.f);
    const float* ep = enc + ((size_t)b * TT_ + t0) * DENC + e;
#pragma unroll 4
    for (int t = 0; t < 128; ++t) {
        float2 v = *(const float2*)(ep + (size_t)t * DENC);
        acc.x += ws[t] * v.x;
        acc.y += ws[t] * v.y;
    }
    *(float2*)&g_ctxp[((size_t)ck * BB + b) * DENC + e] = acc;
}

__global__ void ctx_reduce_kernel(float* __restrict__ out) {
    int b = blockIdx.x, e = threadIdx.x;
    float s = 0.f;
#pragma unroll
    for (int c = 0; c < 8; ++c) s += g_ctxp[((size_t)c * BB + b) * DENC + e];
    out[b * DENC + e] = s;
}

// ---------------- launch ----------------
extern "C" void kernel_launch(void* const* d_in, const int* in_sizes, int n_in,
                              void* d_out, int out_size) {
    const float* mel      = (const float*)d_in[0];
    const float* enc      = (const float*)d_in[1];
    const float* cum      = (const float*)d_in[2];
    const int*   mask     = (const int*)d_in[3];
    const float* w_in     = (const float*)d_in[4];
    const float* b_in     = (const float*)d_in[5];
    const float* w_enc    = (const float*)d_in[6];
    const float* conv_w   = (const float*)d_in[7];
    const float* w_loc    = (const float*)d_in[8];
    const float* w_energy = (const float*)d_in[9];
    float* out = (float*)d_out;

    cudaFuncSetAttribute(gemm_energy_kernel,
                         cudaFuncAttributeMaxDynamicSharedMemorySize, SMEM_DYN);

    conv_kernel<<<BB, 256>>>(cum, conv_w);
    melproj_kernel<<<BB, 512>>>(mel, w_in, b_in);
    prep_w_kernel<<<AA, 144>>>(w_enc, w_loc);
    gemm_energy_kernel<<<512, 256, SMEM_DYN>>>(enc, w_energy);
    softmax_kernel<<<BB, 256>>>(mask, out);
    dim3 gc(8, BB);
    ctx_part_kernel<<<gc, 256>>>(enc, out);
    ctx_reduce_kernel<<<BB, 512>>>(out);
}